// round 9
// baseline (speedup 1.0000x reference)
#include <cuda_runtime.h>
#include <math.h>
#include <stdint.h>

// Problem constants (fixed-shape problem)
#define BATCH 32
#define SEQ   128
#define IDIM  1024
#define HDIM  1024
#define GDIM  4096   // 4*HDIM
#define VOCAB 32000

// ---------------- scratch (device globals; no cudaMalloc allowed) ----------------
__device__ float g_xg[SEQ * BATCH * GDIM];     // precomputed input gates (S,B,4H) : 64 MB
__device__ float g_h[BATCH * HDIM];            // current hidden state
__device__ float g_c[BATCH * HDIM];            // current cell state
__device__ float g_hs[SEQ * BATCH * HDIM];     // all hidden states (S,B,H) : 16 MB
__device__ float g_part[4 * BATCH * GDIM];     // K-split partial gate sums : 2 MB

// ---------------- packed f32x2 helpers (full-rate fp32 on sm_103a) ----------------
__device__ __forceinline__ unsigned long long pk2(float x) {
    unsigned long long r; unsigned u = __float_as_uint(x);
    asm("mov.b64 %0, {%1, %1};" : "=l"(r) : "r"(u));
    return r;
}
__device__ __forceinline__ unsigned long long pkab(float x, float y) {
    unsigned long long r;
    asm("mov.b64 %0, {%1, %2};" : "=l"(r) : "r"(__float_as_uint(x)), "r"(__float_as_uint(y)));
    return r;
}
__device__ __forceinline__ void fma2(unsigned long long& d, unsigned long long a, unsigned long long b) {
    asm("fma.rn.f32x2 %0, %1, %2, %0;" : "+l"(d) : "l"(a), "l"(b));
}
__device__ __forceinline__ float2 up2(unsigned long long v) {
    unsigned lo, hi;
    asm("mov.b64 {%0, %1}, %2;" : "=r"(lo), "=r"(hi) : "l"(v));
    return make_float2(__uint_as_float(lo), __uint_as_float(hi));
}

__device__ __forceinline__ float sigmoidf_(float x) { return 1.0f / (1.0f + expf(-x)); }

// ===================================================================================
// Kernel Z: zero h/c state (needed every replay; d_out/globals persist across replays)
// ===================================================================================
__global__ void k_zero() {
    int i = blockIdx.x * blockDim.x + threadIdx.x;
    if (i < BATCH * HDIM) { g_h[i] = 0.0f; g_c[i] = 0.0f; }
}

// ===================================================================================
// Kernel A: x_gates = gather(emb, ids) @ w_ih^T + b_ih + b_hh
//   GEMM NT: M=4096 (m = s*32+b), N=4096, K=1024. 128x128x8 tiles, 256 thr, 8x8/thr.
// ===================================================================================
__global__ __launch_bounds__(256) void k_xgates(
    const int* __restrict__ ids, const float* __restrict__ emb,
    const float* __restrict__ w_ih, const float* __restrict__ b_ih,
    const float* __restrict__ b_hh)
{
    __shared__ float As[8][128];
    __shared__ float Bs[8][128];

    const int t    = threadIdx.x;
    const int lrow = t >> 1;
    const int koff = (t & 1) * 4;
    const int m0   = blockIdx.y * 128;
    const int n0   = blockIdx.x * 128;

    // gather: global row m -> (s, b); id = input_ids[b*SEQ + s]
    const int m = m0 + lrow;
    const int s = m >> 5;
    const int b = m & 31;
    const float* arow = emb  + (size_t)ids[b * SEQ + s] * IDIM;
    const float* brow = w_ih + (size_t)(n0 + lrow) * IDIM;

    const int ty = t >> 4, tx = t & 15;
    const int rm = ty * 4;   // rows rm..rm+3 and rm+64..rm+67
    const int cn = tx * 4;   // cols cn..cn+3 and cn+64..cn+67

    unsigned long long acc[8][4];
#pragma unroll
    for (int i = 0; i < 8; i++)
#pragma unroll
        for (int j = 0; j < 4; j++) acc[i][j] = 0ull;

    for (int k0 = 0; k0 < IDIM; k0 += 8) {
        float4 av = *(const float4*)(arow + k0 + koff);
        float4 bv = *(const float4*)(brow + k0 + koff);
        __syncthreads();
        As[koff + 0][lrow] = av.x; As[koff + 1][lrow] = av.y;
        As[koff + 2][lrow] = av.z; As[koff + 3][lrow] = av.w;
        Bs[koff + 0][lrow] = bv.x; Bs[koff + 1][lrow] = bv.y;
        Bs[koff + 2][lrow] = bv.z; Bs[koff + 3][lrow] = bv.w;
        __syncthreads();
#pragma unroll
        for (int k = 0; k < 8; k++) {
            float4 a0 = *(const float4*)&As[k][rm];
            float4 a1 = *(const float4*)&As[k][rm + 64];
            float4 b0 = *(const float4*)&Bs[k][cn];
            float4 b1 = *(const float4*)&Bs[k][cn + 64];
            unsigned long long ap[8], bp[4];
            ap[0] = pk2(a0.x); ap[1] = pk2(a0.y); ap[2] = pk2(a0.z); ap[3] = pk2(a0.w);
            ap[4] = pk2(a1.x); ap[5] = pk2(a1.y); ap[6] = pk2(a1.z); ap[7] = pk2(a1.w);
            bp[0] = pkab(b0.x, b0.y); bp[1] = pkab(b0.z, b0.w);
            bp[2] = pkab(b1.x, b1.y); bp[3] = pkab(b1.z, b1.w);
#pragma unroll
            for (int i = 0; i < 8; i++)
#pragma unroll
                for (int j = 0; j < 4; j++) fma2(acc[i][j], ap[i], bp[j]);
        }
    }

    // bias
    float bi[8];
#pragma unroll
    for (int j = 0; j < 4; j++) {
        bi[j]     = b_ih[n0 + cn + j]      + b_hh[n0 + cn + j];
        bi[4 + j] = b_ih[n0 + cn + 64 + j] + b_hh[n0 + cn + 64 + j];
    }

#pragma unroll
    for (int i = 0; i < 8; i++) {
        int row = m0 + ((i < 4) ? (rm + i) : (64 + rm + i - 4));
        float* dst = g_xg + (size_t)row * GDIM + n0;
        float2 f0 = up2(acc[i][0]), f1 = up2(acc[i][1]);
        float2 f2 = up2(acc[i][2]), f3 = up2(acc[i][3]);
        *(float4*)(dst + cn)      = make_float4(f0.x + bi[0], f0.y + bi[1], f1.x + bi[2], f1.y + bi[3]);
        *(float4*)(dst + cn + 64) = make_float4(f2.x + bi[4], f2.y + bi[5], f3.x + bi[6], f3.y + bi[7]);
    }
}

// ===================================================================================
// Kernel B1: per-step recurrent partial GEMM.
//   part[p][b][r] = sum_{k in chunk p (256 wide)} h[b][k] * w_hh[r][k]
//   Grid (32 r-tiles of 128, 4 k-chunks) x 128 threads. Thread tile 4(b) x 8(r).
// ===================================================================================
__global__ __launch_bounds__(128) void k_gates(const float* __restrict__ w_hh)
{
    __shared__ float Hs[16][32];
    __shared__ float Ws[16][128];

    const int t      = threadIdx.x;
    const int rbase  = blockIdx.x * 128;
    const int p      = blockIdx.y;
    const int kstart = p * 256;

    // H load map: one float4 per thread per iter
    const int hb = t >> 2;          // 0..31 (batch row)
    const int hk = (t & 3) * 4;     // 0,4,8,12

    // W load map: 4 float4 per thread per iter (precomputable)
    int wrow[4], wk4[4];
#pragma unroll
    for (int q = 0; q < 4; q++) {
        int idx = q * 128 + t;
        wrow[q] = idx >> 2;
        wk4[q]  = (idx & 3) * 4;
    }

    const int tm  = t & 7;    // batch group
    const int tn  = t >> 3;   // 0..15 (r group)
    const int rb4 = tm * 4;
    const int rc8 = tn * 8;

    unsigned long long acc[4][4];
#pragma unroll
    for (int i = 0; i < 4; i++)
#pragma unroll
        for (int j = 0; j < 4; j++) acc[i][j] = 0ull;

    for (int kt = 0; kt < 256; kt += 16) {
        const int kb = kstart + kt;
        float4 hv = *(const float4*)(g_h + (size_t)hb * HDIM + kb + hk);
        float4 wv[4];
#pragma unroll
        for (int q = 0; q < 4; q++)
            wv[q] = *(const float4*)(w_hh + (size_t)(rbase + wrow[q]) * HDIM + kb + wk4[q]);

        __syncthreads();
        Hs[hk + 0][hb] = hv.x; Hs[hk + 1][hb] = hv.y;
        Hs[hk + 2][hb] = hv.z; Hs[hk + 3][hb] = hv.w;
#pragma unroll
        for (int q = 0; q < 4; q++) {
            Ws[wk4[q] + 0][wrow[q]] = wv[q].x; Ws[wk4[q] + 1][wrow[q]] = wv[q].y;
            Ws[wk4[q] + 2][wrow[q]] = wv[q].z; Ws[wk4[q] + 3][wrow[q]] = wv[q].w;
        }
        __syncthreads();

#pragma unroll
        for (int k = 0; k < 16; k++) {
            float4 ha = *(const float4*)&Hs[k][rb4];
            float4 w0 = *(const float4*)&Ws[k][rc8];
            float4 w1 = *(const float4*)&Ws[k][rc8 + 4];
            unsigned long long a0 = pk2(ha.x), a1 = pk2(ha.y), a2 = pk2(ha.z), a3 = pk2(ha.w);
            unsigned long long b0 = pkab(w0.x, w0.y), b1 = pkab(w0.z, w0.w);
            unsigned long long b2 = pkab(w1.x, w1.y), b3 = pkab(w1.z, w1.w);
            fma2(acc[0][0], a0, b0); fma2(acc[0][1], a0, b1); fma2(acc[0][2], a0, b2); fma2(acc[0][3], a0, b3);
            fma2(acc[1][0], a1, b0); fma2(acc[1][1], a1, b1); fma2(acc[1][2], a1, b2); fma2(acc[1][3], a1, b3);
            fma2(acc[2][0], a2, b0); fma2(acc[2][1], a2, b1); fma2(acc[2][2], a2, b2); fma2(acc[2][3], a2, b3);
            fma2(acc[3][0], a3, b0); fma2(acc[3][1], a3, b1); fma2(acc[3][2], a3, b2); fma2(acc[3][3], a3, b3);
        }
    }

#pragma unroll
    for (int i = 0; i < 4; i++) {
        const int b = rb4 + i;
        float* dst = g_part + ((size_t)(p * BATCH) + b) * GDIM + rbase + rc8;
        float2 f0 = up2(acc[i][0]), f1 = up2(acc[i][1]);
        float2 f2 = up2(acc[i][2]), f3 = up2(acc[i][3]);
        *(float4*)(dst)     = make_float4(f0.x, f0.y, f1.x, f1.y);
        *(float4*)(dst + 4) = make_float4(f2.x, f2.y, f3.x, f3.y);
    }
}

// ===================================================================================
// Kernel B2: per-step gate nonlinearity + state update.
//   gates = xg[s] + sum_p part[p]; i,f,o = sigmoid; g = tanh; c,h update; store hs[s].
// ===================================================================================
__global__ __launch_bounds__(256) void k_update(int s)
{
    const int idx = blockIdx.x * blockDim.x + threadIdx.x;   // < 32768
    const int b = idx >> 10;
    const int j = idx & 1023;

    const float* xb = g_xg + ((size_t)s * BATCH + b) * GDIM;

    float v[4];
#pragma unroll
    for (int q = 0; q < 4; q++) {
        float acc = xb[q * 1024 + j];
#pragma unroll
        for (int p = 0; p < 4; p++)
            acc += g_part[((size_t)(p * BATCH) + b) * GDIM + q * 1024 + j];
        v[q] = acc;
    }

    const float iv = sigmoidf_(v[0]);
    const float fv = sigmoidf_(v[1]);
    const float gv = tanhf(v[2]);
    const float ov = sigmoidf_(v[3]);

    const float cc = fv * g_c[idx] + iv * gv;
    const float hh = ov * tanhf(cc);

    g_c[idx] = cc;
    g_h[idx] = hh;
    g_hs[((size_t)s * BATCH + b) * HDIM + j] = hh;
}

// ===================================================================================
// Kernel C: output projection.  out[m][v] = hs_row(m) . w_out[v] + b_out[v]
//   m -> b = m / rows_per_b, s = ctx + m % rows_per_b.  GEMM NT M=2816,N=32000,K=1024.
// ===================================================================================
__global__ __launch_bounds__(256) void k_out(
    const float* __restrict__ w_out, const float* __restrict__ b_out,
    float* __restrict__ out, int ctx, int rows_per_b, int rows)
{
    __shared__ float As[8][128];
    __shared__ float Bs[8][128];

    const int t    = threadIdx.x;
    const int lrow = t >> 1;
    const int koff = (t & 1) * 4;
    const int m0   = blockIdx.y * 128;
    const int n0   = blockIdx.x * 128;

    const int m  = m0 + lrow;
    const int mc = (m < rows) ? m : (rows - 1);
    const int b  = mc / rows_per_b;
    const int sr = ctx + (mc % rows_per_b);
    const float* arow = g_hs  + ((size_t)sr * BATCH + b) * HDIM;
    const float* brow = w_out + (size_t)(n0 + lrow) * HDIM;

    const int ty = t >> 4, tx = t & 15;
    const int rm = ty * 4;
    const int cn = tx * 4;

    unsigned long long acc[8][4];
#pragma unroll
    for (int i = 0; i < 8; i++)
#pragma unroll
        for (int j = 0; j < 4; j++) acc[i][j] = 0ull;

    for (int k0 = 0; k0 < HDIM; k0 += 8) {
        float4 av = *(const float4*)(arow + k0 + koff);
        float4 bv = *(const float4*)(brow + k0 + koff);
        __syncthreads();
        As[koff + 0][lrow] = av.x; As[koff + 1][lrow] = av.y;
        As[koff + 2][lrow] = av.z; As[koff + 3][lrow] = av.w;
        Bs[koff + 0][lrow] = bv.x; Bs[koff + 1][lrow] = bv.y;
        Bs[koff + 2][lrow] = bv.z; Bs[koff + 3][lrow] = bv.w;
        __syncthreads();
#pragma unroll
        for (int k = 0; k < 8; k++) {
            float4 a0 = *(const float4*)&As[k][rm];
            float4 a1 = *(const float4*)&As[k][rm + 64];
            float4 b0 = *(const float4*)&Bs[k][cn];
            float4 b1 = *(const float4*)&Bs[k][cn + 64];
            unsigned long long ap[8], bp[4];
            ap[0] = pk2(a0.x); ap[1] = pk2(a0.y); ap[2] = pk2(a0.z); ap[3] = pk2(a0.w);
            ap[4] = pk2(a1.x); ap[5] = pk2(a1.y); ap[6] = pk2(a1.z); ap[7] = pk2(a1.w);
            bp[0] = pkab(b0.x, b0.y); bp[1] = pkab(b0.z, b0.w);
            bp[2] = pkab(b1.x, b1.y); bp[3] = pkab(b1.z, b1.w);
#pragma unroll
            for (int i = 0; i < 8; i++)
#pragma unroll
                for (int j = 0; j < 4; j++) fma2(acc[i][j], ap[i], bp[j]);
        }
    }

    float bi[8];
#pragma unroll
    for (int j = 0; j < 4; j++) {
        bi[j]     = b_out[n0 + cn + j];
        bi[4 + j] = b_out[n0 + cn + 64 + j];
    }

#pragma unroll
    for (int i = 0; i < 8; i++) {
        int row = m0 + ((i < 4) ? (rm + i) : (64 + rm + i - 4));
        if (row < rows) {
            float* dst = out + (size_t)row * VOCAB + n0;
            float2 f0 = up2(acc[i][0]), f1 = up2(acc[i][1]);
            float2 f2 = up2(acc[i][2]), f3 = up2(acc[i][3]);
            *(float4*)(dst + cn)      = make_float4(f0.x + bi[0], f0.y + bi[1], f1.x + bi[2], f1.y + bi[3]);
            *(float4*)(dst + cn + 64) = make_float4(f2.x + bi[4], f2.y + bi[5], f3.x + bi[6], f3.y + bi[7]);
        }
    }
}

// ===================================================================================
// kernel_launch: zero state -> input GEMM -> 128 x (gates GEMM, update) -> output GEMM
// All on default stream (graph-capturable, no sync, no alloc).
// ===================================================================================
extern "C" void kernel_launch(void* const* d_in, const int* in_sizes, int n_in,
                              void* d_out, int out_size)
{
    const int*   ids   = (const int*)  d_in[0];
    const float* emb   = (const float*)d_in[1];
    const float* w_ih  = (const float*)d_in[2];
    const float* w_hh  = (const float*)d_in[3];
    const float* b_ih  = (const float*)d_in[4];
    const float* b_hh  = (const float*)d_in[5];
    const float* w_out = (const float*)d_in[6];
    const float* b_out = (const float*)d_in[7];
    float* out = (float*)d_out;

    // derive context length from output size (avoids device-scalar read)
    const int rows       = out_size / VOCAB;     // (S - ctx) * B
    const int rows_per_b = rows / BATCH;         // S - ctx
    const int ctx        = SEQ - rows_per_b;

    // 0) zero h/c state (must happen every call — state persists across graph replays)
    k_zero<<<128, 256>>>();

    // 1) x_gates = gather(emb) @ w_ih^T + b_ih + b_hh
    k_xgates<<<dim3(32, 32), 256>>>(ids, emb, w_ih, b_ih, b_hh);

    // 2) recurrent scan: 128 steps, 2 kernels each
    for (int s = 0; s < SEQ; s++) {
        k_gates<<<dim3(32, 4), 128>>>(w_hh);
        k_update<<<128, 256>>>(s);
    }

    // 3) output projection
    const int mtiles = (rows + 127) / 128;
    k_out<<<dim3(VOCAB / 128, mtiles), 256>>>(w_out, b_out, out, ctx, rows_per_b, rows);
}

// round 10
// speedup vs baseline: 1.0006x; 1.0006x over previous
#include <cuda_runtime.h>
#include <math.h>
#include <stdint.h>

// Problem constants (fixed-shape problem)
#define BATCH 32
#define SEQ   128
#define IDIM  1024
#define HDIM  1024
#define GDIM  4096   // 4*HDIM
#define VOCAB 32000

// ---------------- scratch (device globals; no cudaMalloc allowed) ----------------
__device__ float g_xg[SEQ * BATCH * GDIM];     // precomputed input gates (S,B,4H) : 64 MB
__device__ float g_h[BATCH * HDIM];            // current hidden state
__device__ float g_c[BATCH * HDIM];            // current cell state
__device__ float g_hs[SEQ * BATCH * HDIM];     // all hidden states (S,B,H) : 16 MB
__device__ float g_part[4 * BATCH * GDIM];     // K-split partial gate sums : 2 MB

// ---------------- packed f32x2 helpers (full-rate fp32 on sm_103a) ----------------
__device__ __forceinline__ unsigned long long pk2(float x) {
    unsigned long long r; unsigned u = __float_as_uint(x);
    asm("mov.b64 %0, {%1, %1};" : "=l"(r) : "r"(u));
    return r;
}
__device__ __forceinline__ unsigned long long pkab(float x, float y) {
    unsigned long long r;
    asm("mov.b64 %0, {%1, %2};" : "=l"(r) : "r"(__float_as_uint(x)), "r"(__float_as_uint(y)));
    return r;
}
__device__ __forceinline__ void fma2(unsigned long long& d, unsigned long long a, unsigned long long b) {
    asm("fma.rn.f32x2 %0, %1, %2, %0;" : "+l"(d) : "l"(a), "l"(b));
}
__device__ __forceinline__ float2 up2(unsigned long long v) {
    unsigned lo, hi;
    asm("mov.b64 {%0, %1}, %2;" : "=r"(lo), "=r"(hi) : "l"(v));
    return make_float2(__uint_as_float(lo), __uint_as_float(hi));
}

__device__ __forceinline__ float sigmoidf_(float x) { return 1.0f / (1.0f + expf(-x)); }

// ===================================================================================
// Kernel Z: zero h/c state (needed every replay; d_out/globals persist across replays)
// ===================================================================================
__global__ void k_zero() {
    int i = blockIdx.x * blockDim.x + threadIdx.x;
    if (i < BATCH * HDIM) { g_h[i] = 0.0f; g_c[i] = 0.0f; }
}

// ===================================================================================
// Kernel A: x_gates = gather(emb, ids) @ w_ih^T + b_ih + b_hh
//   GEMM NT: M=4096 (m = s*32+b), N=4096, K=1024. 128x128x8 tiles, 256 thr, 8x8/thr.
// ===================================================================================
__global__ __launch_bounds__(256) void k_xgates(
    const int* __restrict__ ids, const float* __restrict__ emb,
    const float* __restrict__ w_ih, const float* __restrict__ b_ih,
    const float* __restrict__ b_hh)
{
    __shared__ float As[8][128];
    __shared__ float Bs[8][128];

    const int t    = threadIdx.x;
    const int lrow = t >> 1;
    const int koff = (t & 1) * 4;
    const int m0   = blockIdx.y * 128;
    const int n0   = blockIdx.x * 128;

    // gather: global row m -> (s, b); id = input_ids[b*SEQ + s]
    const int m = m0 + lrow;
    const int s = m >> 5;
    const int b = m & 31;
    const float* arow = emb  + (size_t)ids[b * SEQ + s] * IDIM;
    const float* brow = w_ih + (size_t)(n0 + lrow) * IDIM;

    const int ty = t >> 4, tx = t & 15;
    const int rm = ty * 4;   // rows rm..rm+3 and rm+64..rm+67
    const int cn = tx * 4;   // cols cn..cn+3 and cn+64..cn+67

    unsigned long long acc[8][4];
#pragma unroll
    for (int i = 0; i < 8; i++)
#pragma unroll
        for (int j = 0; j < 4; j++) acc[i][j] = 0ull;

    for (int k0 = 0; k0 < IDIM; k0 += 8) {
        float4 av = *(const float4*)(arow + k0 + koff);
        float4 bv = *(const float4*)(brow + k0 + koff);
        __syncthreads();
        As[koff + 0][lrow] = av.x; As[koff + 1][lrow] = av.y;
        As[koff + 2][lrow] = av.z; As[koff + 3][lrow] = av.w;
        Bs[koff + 0][lrow] = bv.x; Bs[koff + 1][lrow] = bv.y;
        Bs[koff + 2][lrow] = bv.z; Bs[koff + 3][lrow] = bv.w;
        __syncthreads();
#pragma unroll
        for (int k = 0; k < 8; k++) {
            float4 a0 = *(const float4*)&As[k][rm];
            float4 a1 = *(const float4*)&As[k][rm + 64];
            float4 b0 = *(const float4*)&Bs[k][cn];
            float4 b1 = *(const float4*)&Bs[k][cn + 64];
            unsigned long long ap[8], bp[4];
            ap[0] = pk2(a0.x); ap[1] = pk2(a0.y); ap[2] = pk2(a0.z); ap[3] = pk2(a0.w);
            ap[4] = pk2(a1.x); ap[5] = pk2(a1.y); ap[6] = pk2(a1.z); ap[7] = pk2(a1.w);
            bp[0] = pkab(b0.x, b0.y); bp[1] = pkab(b0.z, b0.w);
            bp[2] = pkab(b1.x, b1.y); bp[3] = pkab(b1.z, b1.w);
#pragma unroll
            for (int i = 0; i < 8; i++)
#pragma unroll
                for (int j = 0; j < 4; j++) fma2(acc[i][j], ap[i], bp[j]);
        }
    }

    // bias
    float bi[8];
#pragma unroll
    for (int j = 0; j < 4; j++) {
        bi[j]     = b_ih[n0 + cn + j]      + b_hh[n0 + cn + j];
        bi[4 + j] = b_ih[n0 + cn + 64 + j] + b_hh[n0 + cn + 64 + j];
    }

#pragma unroll
    for (int i = 0; i < 8; i++) {
        int row = m0 + ((i < 4) ? (rm + i) : (64 + rm + i - 4));
        float* dst = g_xg + (size_t)row * GDIM + n0;
        float2 f0 = up2(acc[i][0]), f1 = up2(acc[i][1]);
        float2 f2 = up2(acc[i][2]), f3 = up2(acc[i][3]);
        *(float4*)(dst + cn)      = make_float4(f0.x + bi[0], f0.y + bi[1], f1.x + bi[2], f1.y + bi[3]);
        *(float4*)(dst + cn + 64) = make_float4(f2.x + bi[4], f2.y + bi[5], f3.x + bi[6], f3.y + bi[7]);
    }
}

// ===================================================================================
// Kernel B1: per-step recurrent partial GEMM.
//   part[p][b][r] = sum_{k in chunk p (256 wide)} h[b][k] * w_hh[r][k]
//   Grid (32 r-tiles of 128, 4 k-chunks) x 128 threads. Thread tile 4(b) x 8(r).
// ===================================================================================
__global__ __launch_bounds__(128) void k_gates(const float* __restrict__ w_hh)
{
    __shared__ float Hs[16][32];
    __shared__ float Ws[16][128];

    const int t      = threadIdx.x;
    const int rbase  = blockIdx.x * 128;
    const int p      = blockIdx.y;
    const int kstart = p * 256;

    // H load map: one float4 per thread per iter
    const int hb = t >> 2;          // 0..31 (batch row)
    const int hk = (t & 3) * 4;     // 0,4,8,12

    // W load map: 4 float4 per thread per iter (precomputable)
    int wrow[4], wk4[4];
#pragma unroll
    for (int q = 0; q < 4; q++) {
        int idx = q * 128 + t;
        wrow[q] = idx >> 2;
        wk4[q]  = (idx & 3) * 4;
    }

    const int tm  = t & 7;    // batch group
    const int tn  = t >> 3;   // 0..15 (r group)
    const int rb4 = tm * 4;
    const int rc8 = tn * 8;

    unsigned long long acc[4][4];
#pragma unroll
    for (int i = 0; i < 4; i++)
#pragma unroll
        for (int j = 0; j < 4; j++) acc[i][j] = 0ull;

    for (int kt = 0; kt < 256; kt += 16) {
        const int kb = kstart + kt;
        float4 hv = *(const float4*)(g_h + (size_t)hb * HDIM + kb + hk);
        float4 wv[4];
#pragma unroll
        for (int q = 0; q < 4; q++)
            wv[q] = *(const float4*)(w_hh + (size_t)(rbase + wrow[q]) * HDIM + kb + wk4[q]);

        __syncthreads();
        Hs[hk + 0][hb] = hv.x; Hs[hk + 1][hb] = hv.y;
        Hs[hk + 2][hb] = hv.z; Hs[hk + 3][hb] = hv.w;
#pragma unroll
        for (int q = 0; q < 4; q++) {
            Ws[wk4[q] + 0][wrow[q]] = wv[q].x; Ws[wk4[q] + 1][wrow[q]] = wv[q].y;
            Ws[wk4[q] + 2][wrow[q]] = wv[q].z; Ws[wk4[q] + 3][wrow[q]] = wv[q].w;
        }
        __syncthreads();

#pragma unroll
        for (int k = 0; k < 16; k++) {
            float4 ha = *(const float4*)&Hs[k][rb4];
            float4 w0 = *(const float4*)&Ws[k][rc8];
            float4 w1 = *(const float4*)&Ws[k][rc8 + 4];
            unsigned long long a0 = pk2(ha.x), a1 = pk2(ha.y), a2 = pk2(ha.z), a3 = pk2(ha.w);
            unsigned long long b0 = pkab(w0.x, w0.y), b1 = pkab(w0.z, w0.w);
            unsigned long long b2 = pkab(w1.x, w1.y), b3 = pkab(w1.z, w1.w);
            fma2(acc[0][0], a0, b0); fma2(acc[0][1], a0, b1); fma2(acc[0][2], a0, b2); fma2(acc[0][3], a0, b3);
            fma2(acc[1][0], a1, b0); fma2(acc[1][1], a1, b1); fma2(acc[1][2], a1, b2); fma2(acc[1][3], a1, b3);
            fma2(acc[2][0], a2, b0); fma2(acc[2][1], a2, b1); fma2(acc[2][2], a2, b2); fma2(acc[2][3], a2, b3);
            fma2(acc[3][0], a3, b0); fma2(acc[3][1], a3, b1); fma2(acc[3][2], a3, b2); fma2(acc[3][3], a3, b3);
        }
    }

#pragma unroll
    for (int i = 0; i < 4; i++) {
        const int b = rb4 + i;
        float* dst = g_part + ((size_t)(p * BATCH) + b) * GDIM + rbase + rc8;
        float2 f0 = up2(acc[i][0]), f1 = up2(acc[i][1]);
        float2 f2 = up2(acc[i][2]), f3 = up2(acc[i][3]);
        *(float4*)(dst)     = make_float4(f0.x, f0.y, f1.x, f1.y);
        *(float4*)(dst + 4) = make_float4(f2.x, f2.y, f3.x, f3.y);
    }
}

// ===================================================================================
// Kernel B2: per-step gate nonlinearity + state update.
//   gates = xg[s] + sum_p part[p]; i,f,o = sigmoid; g = tanh; c,h update; store hs[s].
// ===================================================================================
__global__ __launch_bounds__(256) void k_update(int s)
{
    const int idx = blockIdx.x * blockDim.x + threadIdx.x;   // < 32768
    const int b = idx >> 10;
    const int j = idx & 1023;

    const float* xb = g_xg + ((size_t)s * BATCH + b) * GDIM;

    float v[4];
#pragma unroll
    for (int q = 0; q < 4; q++) {
        float acc = xb[q * 1024 + j];
#pragma unroll
        for (int p = 0; p < 4; p++)
            acc += g_part[((size_t)(p * BATCH) + b) * GDIM + q * 1024 + j];
        v[q] = acc;
    }

    const float iv = sigmoidf_(v[0]);
    const float fv = sigmoidf_(v[1]);
    const float gv = tanhf(v[2]);
    const float ov = sigmoidf_(v[3]);

    const float cc = fv * g_c[idx] + iv * gv;
    const float hh = ov * tanhf(cc);

    g_c[idx] = cc;
    g_h[idx] = hh;
    g_hs[((size_t)s * BATCH + b) * HDIM + j] = hh;
}

// ===================================================================================
// Kernel C: output projection.  out[m][v] = hs_row(m) . w_out[v] + b_out[v]
//   m -> b = m / rows_per_b, s = ctx + m % rows_per_b.  GEMM NT M=2816,N=32000,K=1024.
// ===================================================================================
__global__ __launch_bounds__(256) void k_out(
    const float* __restrict__ w_out, const float* __restrict__ b_out,
    float* __restrict__ out, int ctx, int rows_per_b, int rows)
{
    __shared__ float As[8][128];
    __shared__ float Bs[8][128];

    const int t    = threadIdx.x;
    const int lrow = t >> 1;
    const int koff = (t & 1) * 4;
    const int m0   = blockIdx.y * 128;
    const int n0   = blockIdx.x * 128;

    const int m  = m0 + lrow;
    const int mc = (m < rows) ? m : (rows - 1);
    const int b  = mc / rows_per_b;
    const int sr = ctx + (mc % rows_per_b);
    const float* arow = g_hs  + ((size_t)sr * BATCH + b) * HDIM;
    const float* brow = w_out + (size_t)(n0 + lrow) * HDIM;

    const int ty = t >> 4, tx = t & 15;
    const int rm = ty * 4;
    const int cn = tx * 4;

    unsigned long long acc[8][4];
#pragma unroll
    for (int i = 0; i < 8; i++)
#pragma unroll
        for (int j = 0; j < 4; j++) acc[i][j] = 0ull;

    for (int k0 = 0; k0 < HDIM; k0 += 8) {
        float4 av = *(const float4*)(arow + k0 + koff);
        float4 bv = *(const float4*)(brow + k0 + koff);
        __syncthreads();
        As[koff + 0][lrow] = av.x; As[koff + 1][lrow] = av.y;
        As[koff + 2][lrow] = av.z; As[koff + 3][lrow] = av.w;
        Bs[koff + 0][lrow] = bv.x; Bs[koff + 1][lrow] = bv.y;
        Bs[koff + 2][lrow] = bv.z; Bs[koff + 3][lrow] = bv.w;
        __syncthreads();
#pragma unroll
        for (int k = 0; k < 8; k++) {
            float4 a0 = *(const float4*)&As[k][rm];
            float4 a1 = *(const float4*)&As[k][rm + 64];
            float4 b0 = *(const float4*)&Bs[k][cn];
            float4 b1 = *(const float4*)&Bs[k][cn + 64];
            unsigned long long ap[8], bp[4];
            ap[0] = pk2(a0.x); ap[1] = pk2(a0.y); ap[2] = pk2(a0.z); ap[3] = pk2(a0.w);
            ap[4] = pk2(a1.x); ap[5] = pk2(a1.y); ap[6] = pk2(a1.z); ap[7] = pk2(a1.w);
            bp[0] = pkab(b0.x, b0.y); bp[1] = pkab(b0.z, b0.w);
            bp[2] = pkab(b1.x, b1.y); bp[3] = pkab(b1.z, b1.w);
#pragma unroll
            for (int i = 0; i < 8; i++)
#pragma unroll
                for (int j = 0; j < 4; j++) fma2(acc[i][j], ap[i], bp[j]);
        }
    }

    float bi[8];
#pragma unroll
    for (int j = 0; j < 4; j++) {
        bi[j]     = b_out[n0 + cn + j];
        bi[4 + j] = b_out[n0 + cn + 64 + j];
    }

#pragma unroll
    for (int i = 0; i < 8; i++) {
        int row = m0 + ((i < 4) ? (rm + i) : (64 + rm + i - 4));
        if (row < rows) {
            float* dst = out + (size_t)row * VOCAB + n0;
            float2 f0 = up2(acc[i][0]), f1 = up2(acc[i][1]);
            float2 f2 = up2(acc[i][2]), f3 = up2(acc[i][3]);
            *(float4*)(dst + cn)      = make_float4(f0.x + bi[0], f0.y + bi[1], f1.x + bi[2], f1.y + bi[3]);
            *(float4*)(dst + cn + 64) = make_float4(f2.x + bi[4], f2.y + bi[5], f3.x + bi[6], f3.y + bi[7]);
        }
    }
}

// ===================================================================================
// kernel_launch: zero state -> input GEMM -> 128 x (gates GEMM, update) -> output GEMM
// All on default stream (graph-capturable, no sync, no alloc).
// ===================================================================================
extern "C" void kernel_launch(void* const* d_in, const int* in_sizes, int n_in,
                              void* d_out, int out_size)
{
    const int*   ids   = (const int*)  d_in[0];
    const float* emb   = (const float*)d_in[1];
    const float* w_ih  = (const float*)d_in[2];
    const float* w_hh  = (const float*)d_in[3];
    const float* b_ih  = (const float*)d_in[4];
    const float* b_hh  = (const float*)d_in[5];
    const float* w_out = (const float*)d_in[6];
    const float* b_out = (const float*)d_in[7];
    float* out = (float*)d_out;

    // derive context length from output size (avoids device-scalar read)
    const int rows       = out_size / VOCAB;     // (S - ctx) * B
    const int rows_per_b = rows / BATCH;         // S - ctx
    const int ctx        = SEQ - rows_per_b;

    // 0) zero h/c state (must happen every call — state persists across graph replays)
    k_zero<<<128, 256>>>();

    // 1) x_gates = gather(emb) @ w_ih^T + b_ih + b_hh
    k_xgates<<<dim3(32, 32), 256>>>(ids, emb, w_ih, b_ih, b_hh);

    // 2) recurrent scan: 128 steps, 2 kernels each
    for (int s = 0; s < SEQ; s++) {
        k_gates<<<dim3(32, 4), 128>>>(w_hh);
        k_update<<<128, 256>>>(s);
    }

    // 3) output projection
    const int mtiles = (rows + 127) / 128;
    k_out<<<dim3(VOCAB / 128, mtiles), 256>>>(w_out, b_out, out, ctx, rows_per_b, rows);
}